// round 2
// baseline (speedup 1.0000x reference)
#include <cuda_runtime.h>

// NonLocalBlock fp32 pipeline for GB300 (sm_103a).
// proj (3x 1x1conv as GEMM) -> flash attention (online softmax) -> zconv(+partial stats)
// -> stats reduce -> LayerNorm + residual. All packed fp32x2 FMA inner loops.

#define BB 4
#define CC 256
#define FF 128
#define NN 4096
#define LN_EPS 1e-5f

typedef unsigned long long ull;

// ---- scratch (allocation-free: __device__ globals) ----
__device__ float g_theta[BB * NN * FF];   // Q rows [b][n][f]
__device__ float g_phi  [BB * NN * FF];   // K rows [b][n][f]
__device__ float g_gv   [BB * NN * FF];   // V rows [b][n][f]
__device__ float g_y    [BB * NN * FF];   // attn output [b][n][f]
__device__ float g_z    [BB * CC * NN];   // pre-LN z [b][c][n]
__device__ float2 g_part[BB * 256];       // per-tile (sum, sumsq)
__device__ float2 g_stats[BB];            // (mean, rstd)

// ---- packed fp32x2 helpers (full-rate fp32 path on sm_103a) ----
__device__ __forceinline__ ull dup2(float x) {
    ull r; asm("mov.b64 %0, {%1, %1};" : "=l"(r) : "f"(x)); return r;
}
__device__ __forceinline__ ull fma2(ull a, ull b, ull c) {
    ull d; asm("fma.rn.f32x2 %0, %1, %2, %3;" : "=l"(d) : "l"(a), "l"(b), "l"(c)); return d;
}
__device__ __forceinline__ ull mul2(ull a, ull b) {
    ull d; asm("mul.rn.f32x2 %0, %1, %2;" : "=l"(d) : "l"(a), "l"(b)); return d;
}
__device__ __forceinline__ float2 upk(ull v) {
    float2 f; asm("mov.b64 {%0, %1}, %2;" : "=f"(f.x), "=f"(f.y) : "l"(v)); return f;
}

// ============================================================================
// proj: out[b,n,f] = sum_c x[b,c,n] * W[f,c] + bias[f]   for theta/phi/g
// grid (NN/64, 2*3, BB), 256 threads, 64x64 tile, 4x4 micro-tile
// ============================================================================
__global__ void __launch_bounds__(256) proj_kernel(
    const float* __restrict__ x,
    const float* __restrict__ Wt, const float* __restrict__ bt,
    const float* __restrict__ Wp, const float* __restrict__ bp,
    const float* __restrict__ Wg, const float* __restrict__ bg)
{
    __shared__ __align__(16) float Xs[16][64];   // [c][n]
    __shared__ __align__(16) float Ws[16][68];   // [c][f] padded

    int b  = blockIdx.z;
    int p  = blockIdx.y >> 1;
    int f0 = (blockIdx.y & 1) * 64;
    int n0 = blockIdx.x * 64;

    const float* W; const float* bias; float* outp;
    if (p == 0)      { W = Wt; bias = bt; outp = g_theta; }
    else if (p == 1) { W = Wp; bias = bp; outp = g_phi;   }
    else             { W = Wg; bias = bg; outp = g_gv;    }

    int tid = threadIdx.x, tx = tid & 15, ty = tid >> 4;
    const float* xb = x + b * CC * NN;

    ull acc[4][2];
#pragma unroll
    for (int i = 0; i < 4; i++) { acc[i][0] = 0ULL; acc[i][1] = 0ULL; }

    for (int k0 = 0; k0 < CC; k0 += 16) {
#pragma unroll
        for (int i = 0; i < 4; i++) {
            int c = i * 4 + (tid >> 6);
            int n = tid & 63;
            Xs[c][n] = xb[(k0 + c) * NN + n0 + n];
        }
#pragma unroll
        for (int i = 0; i < 4; i++) {
            int f = i * 16 + (tid >> 4);
            int c = tid & 15;
            Ws[c][f] = W[(f0 + f) * CC + k0 + c];
        }
        __syncthreads();
#pragma unroll
        for (int k = 0; k < 16; k++) {
            float4 a = *(const float4*)&Xs[k][4 * ty];
            ulonglong2 w2 = *(const ulonglong2*)&Ws[k][4 * tx];
            ull a0 = dup2(a.x), a1 = dup2(a.y), a2 = dup2(a.z), a3 = dup2(a.w);
            acc[0][0] = fma2(a0, w2.x, acc[0][0]); acc[0][1] = fma2(a0, w2.y, acc[0][1]);
            acc[1][0] = fma2(a1, w2.x, acc[1][0]); acc[1][1] = fma2(a1, w2.y, acc[1][1]);
            acc[2][0] = fma2(a2, w2.x, acc[2][0]); acc[2][1] = fma2(a2, w2.y, acc[2][1]);
            acc[3][0] = fma2(a3, w2.x, acc[3][0]); acc[3][1] = fma2(a3, w2.y, acc[3][1]);
        }
        __syncthreads();
    }

    float b0 = bias[f0 + 4 * tx + 0], b1 = bias[f0 + 4 * tx + 1];
    float b2 = bias[f0 + 4 * tx + 2], b3 = bias[f0 + 4 * tx + 3];
#pragma unroll
    for (int i = 0; i < 4; i++) {
        float2 u0 = upk(acc[i][0]), u1 = upk(acc[i][1]);
        float4 w = make_float4(u0.x + b0, u0.y + b1, u1.x + b2, u1.y + b3);
        *(float4*)&outp[(b * NN + n0 + 4 * ty + i) * FF + f0 + 4 * tx] = w;
    }
}

// ============================================================================
// flash attention: per (b, 64-query tile), loop 64-key tiles.
// S = Q K^T (no scaling in ref), online softmax, O += P V, y = O / l.
// 256 threads (16x16); thread owns 4 rows x (4 + 4) cols of O.
// dynamic smem: QsT[128][68] KsT[128][68] Vs[64][128] Ps[64][68]
// ============================================================================
#define ATTN_SMEM ((2 * 128 * 68 + 64 * 128 + 64 * 68) * 4)

__global__ void __launch_bounds__(256) attn_kernel()
{
    extern __shared__ __align__(16) float sm[];
    float* QsT = sm;                       // [f][r] padded 68
    float* KsT = sm + 128 * 68;            // [f][c] padded 68
    float* Vs  = sm + 2 * 128 * 68;        // [n][f]
    float* Ps  = sm + 2 * 128 * 68 + 64 * 128;  // [r][c] padded 68

    int b  = blockIdx.y;
    int n0 = blockIdx.x * 64;
    int tid = threadIdx.x, tx = tid & 15, ty = tid >> 4;

    const float* Qg = g_theta + (b * NN + n0) * FF;
    const float* Kg = g_phi + b * NN * FF;
    const float* Vg = g_gv  + b * NN * FF;

    // stage Q transposed: QsT[f][r]
    for (int i = tid; i < 64 * FF; i += 256) {
        int r = i >> 7, f = i & 127;
        QsT[f * 68 + r] = Qg[r * FF + f];
    }

    float m[4], l[4];
    ull o2[4][4];
#pragma unroll
    for (int i = 0; i < 4; i++) {
        m[i] = -3.0e38f; l[i] = 0.0f;
        o2[i][0] = o2[i][1] = o2[i][2] = o2[i][3] = 0ULL;
    }

    for (int t = 0; t < 64; t++) {
        int nt0 = t * 64;
        __syncthreads();   // previous PV done before overwriting K/V
        for (int i = tid; i < 64 * FF; i += 256) {
            int r = i >> 7, f = i & 127;
            KsT[f * 68 + r] = Kg[(nt0 + r) * FF + f];
        }
        for (int i = tid; i < 64 * FF / 4; i += 256)
            ((float4*)Vs)[i] = ((const float4*)(Vg + nt0 * FF))[i];
        __syncthreads();

        // ---- S = Q K^T ----
        ull s2[4][2];
#pragma unroll
        for (int i = 0; i < 4; i++) { s2[i][0] = 0ULL; s2[i][1] = 0ULL; }
#pragma unroll 8
        for (int k = 0; k < FF; k++) {
            float4 q = *(const float4*)&QsT[k * 68 + 4 * ty];
            ulonglong2 kk = *(const ulonglong2*)&KsT[k * 68 + 4 * tx];
            ull q0 = dup2(q.x), q1 = dup2(q.y), q2 = dup2(q.z), q3 = dup2(q.w);
            s2[0][0] = fma2(q0, kk.x, s2[0][0]); s2[0][1] = fma2(q0, kk.y, s2[0][1]);
            s2[1][0] = fma2(q1, kk.x, s2[1][0]); s2[1][1] = fma2(q1, kk.y, s2[1][1]);
            s2[2][0] = fma2(q2, kk.x, s2[2][0]); s2[2][1] = fma2(q2, kk.y, s2[2][1]);
            s2[3][0] = fma2(q3, kk.x, s2[3][0]); s2[3][1] = fma2(q3, kk.y, s2[3][1]);
        }

        // ---- online softmax (rows spread over 16 lanes sharing ty) ----
#pragma unroll
        for (int i = 0; i < 4; i++) {
            float2 u0 = upk(s2[i][0]), u1 = upk(s2[i][1]);
            float s0 = u0.x, s1 = u0.y, s2v = u1.x, s3 = u1.y;
            float mx = fmaxf(fmaxf(s0, s1), fmaxf(s2v, s3));
            mx = fmaxf(mx, __shfl_xor_sync(0xffffffffu, mx, 1));
            mx = fmaxf(mx, __shfl_xor_sync(0xffffffffu, mx, 2));
            mx = fmaxf(mx, __shfl_xor_sync(0xffffffffu, mx, 4));
            mx = fmaxf(mx, __shfl_xor_sync(0xffffffffu, mx, 8));
            float mn = fmaxf(m[i], mx);
            float al = __expf(m[i] - mn);
            float p0 = __expf(s0 - mn), p1 = __expf(s1 - mn);
            float p2 = __expf(s2v - mn), p3 = __expf(s3 - mn);
            *(float4*)&Ps[(4 * ty + i) * 68 + 4 * tx] = make_float4(p0, p1, p2, p3);
            float su = p0 + p1 + p2 + p3;
            su += __shfl_xor_sync(0xffffffffu, su, 1);
            su += __shfl_xor_sync(0xffffffffu, su, 2);
            su += __shfl_xor_sync(0xffffffffu, su, 4);
            su += __shfl_xor_sync(0xffffffffu, su, 8);
            l[i] = l[i] * al + su;
            m[i] = mn;
            ull ad = dup2(al);
            o2[i][0] = mul2(o2[i][0], ad); o2[i][1] = mul2(o2[i][1], ad);
            o2[i][2] = mul2(o2[i][2], ad); o2[i][3] = mul2(o2[i][3], ad);
        }
        __syncthreads();

        // ---- O += P V ----
#pragma unroll 4
        for (int n = 0; n < 64; n++) {
            float p0 = Ps[(4 * ty + 0) * 68 + n];
            float p1 = Ps[(4 * ty + 1) * 68 + n];
            float p2 = Ps[(4 * ty + 2) * 68 + n];
            float p3 = Ps[(4 * ty + 3) * 68 + n];
            ulonglong2 va = *(const ulonglong2*)&Vs[n * FF + 4 * tx];
            ulonglong2 vb = *(const ulonglong2*)&Vs[n * FF + 64 + 4 * tx];
            ull d0 = dup2(p0), d1 = dup2(p1), d2 = dup2(p2), d3 = dup2(p3);
            o2[0][0] = fma2(d0, va.x, o2[0][0]); o2[0][1] = fma2(d0, va.y, o2[0][1]);
            o2[0][2] = fma2(d0, vb.x, o2[0][2]); o2[0][3] = fma2(d0, vb.y, o2[0][3]);
            o2[1][0] = fma2(d1, va.x, o2[1][0]); o2[1][1] = fma2(d1, va.y, o2[1][1]);
            o2[1][2] = fma2(d1, vb.x, o2[1][2]); o2[1][3] = fma2(d1, vb.y, o2[1][3]);
            o2[2][0] = fma2(d2, va.x, o2[2][0]); o2[2][1] = fma2(d2, va.y, o2[2][1]);
            o2[2][2] = fma2(d2, vb.x, o2[2][2]); o2[2][3] = fma2(d2, vb.y, o2[2][3]);
            o2[3][0] = fma2(d3, va.x, o2[3][0]); o2[3][1] = fma2(d3, va.y, o2[3][1]);
            o2[3][2] = fma2(d3, vb.x, o2[3][2]); o2[3][3] = fma2(d3, vb.y, o2[3][3]);
        }
    }

    float* yb = g_y + (b * NN + n0) * FF;
#pragma unroll
    for (int i = 0; i < 4; i++) {
        float inv = 1.0f / l[i];
        float2 a = upk(o2[i][0]), bb2 = upk(o2[i][1]);
        float2 c = upk(o2[i][2]), d = upk(o2[i][3]);
        *(float4*)&yb[(4 * ty + i) * FF + 4 * tx] =
            make_float4(a.x * inv, a.y * inv, bb2.x * inv, bb2.y * inv);
        *(float4*)&yb[(4 * ty + i) * FF + 64 + 4 * tx] =
            make_float4(c.x * inv, c.y * inv, d.x * inv, d.y * inv);
    }
}

// ============================================================================
// zconv: z[b,c,n] = sum_f Wz[c,f] * y[b,n,f] + bz[c]; emits per-tile LN partials.
// grid (NN/64, CC/64, BB), 256 threads.
// ============================================================================
#define ZCONV_SMEM (2 * 128 * 68 * 4)

__global__ void __launch_bounds__(256) zconv_kernel(
    const float* __restrict__ Wz, const float* __restrict__ bz)
{
    extern __shared__ __align__(16) float sm[];
    float* WzT = sm;              // [f][c] padded 68
    float* YsT = sm + 128 * 68;   // [f][n] padded 68

    int b  = blockIdx.z;
    int c0 = blockIdx.y * 64;
    int n0 = blockIdx.x * 64;
    int tid = threadIdx.x, tx = tid & 15, ty = tid >> 4;

    const float* yb = g_y + b * NN * FF;
    for (int i = tid; i < 64 * FF; i += 256) {
        int c = i >> 7, f = i & 127;
        WzT[f * 68 + c] = Wz[(c0 + c) * FF + f];
    }
    for (int i = tid; i < 64 * FF; i += 256) {
        int n = i >> 7, f = i & 127;
        YsT[f * 68 + n] = yb[(n0 + n) * FF + f];
    }
    __syncthreads();

    ull acc[4][2];
#pragma unroll
    for (int i = 0; i < 4; i++) { acc[i][0] = 0ULL; acc[i][1] = 0ULL; }
#pragma unroll 8
    for (int k = 0; k < FF; k++) {
        float4 a = *(const float4*)&WzT[k * 68 + 4 * ty];
        ulonglong2 yv = *(const ulonglong2*)&YsT[k * 68 + 4 * tx];
        ull a0 = dup2(a.x), a1 = dup2(a.y), a2 = dup2(a.z), a3 = dup2(a.w);
        acc[0][0] = fma2(a0, yv.x, acc[0][0]); acc[0][1] = fma2(a0, yv.y, acc[0][1]);
        acc[1][0] = fma2(a1, yv.x, acc[1][0]); acc[1][1] = fma2(a1, yv.y, acc[1][1]);
        acc[2][0] = fma2(a2, yv.x, acc[2][0]); acc[2][1] = fma2(a2, yv.y, acc[2][1]);
        acc[3][0] = fma2(a3, yv.x, acc[3][0]); acc[3][1] = fma2(a3, yv.y, acc[3][1]);
    }

    float lsum = 0.0f, lsq = 0.0f;
    float* zb = g_z + b * CC * NN;
#pragma unroll
    for (int i = 0; i < 4; i++) {
        float bzv = bz[c0 + 4 * ty + i];
        float2 u0 = upk(acc[i][0]), u1 = upk(acc[i][1]);
        float z0 = u0.x + bzv, z1 = u0.y + bzv, z2 = u1.x + bzv, z3 = u1.y + bzv;
        *(float4*)&zb[(c0 + 4 * ty + i) * NN + n0 + 4 * tx] = make_float4(z0, z1, z2, z3);
        lsum += z0 + z1 + z2 + z3;
        lsq  += z0 * z0 + z1 * z1 + z2 * z2 + z3 * z3;
    }

    __syncthreads();   // done with WzT/YsT; reuse for reduction (deterministic tree)
    float* rs = sm;
    float* rq = sm + 256;
    rs[tid] = lsum; rq[tid] = lsq;
    __syncthreads();
#pragma unroll
    for (int s = 128; s > 0; s >>= 1) {
        if (tid < s) { rs[tid] += rs[tid + s]; rq[tid] += rq[tid + s]; }
        __syncthreads();
    }
    if (tid == 0)
        g_part[b * 256 + blockIdx.y * 64 + blockIdx.x] = make_float2(rs[0], rq[0]);
}

// ============================================================================
// stats: reduce 256 tile-partials per batch -> (mean, rstd)
// ============================================================================
__global__ void stats_kernel()
{
    __shared__ float rs[256], rq[256];
    int b = blockIdx.x, tid = threadIdx.x;
    float2 v = g_part[b * 256 + tid];
    rs[tid] = v.x; rq[tid] = v.y;
    __syncthreads();
#pragma unroll
    for (int s = 128; s > 0; s >>= 1) {
        if (tid < s) { rs[tid] += rs[tid + s]; rq[tid] += rq[tid + s]; }
        __syncthreads();
    }
    if (tid == 0) {
        float inv  = 1.0f / (float)(CC * NN);
        float mean = rs[0] * inv;
        float var  = rq[0] * inv - mean * mean;
        g_stats[b] = make_float2(mean, rsqrtf(var + LN_EPS));
    }
}

// ============================================================================
// LN + affine + residual: out = (z - mu) * rstd * ln_w + ln_b + x
// ============================================================================
__global__ void __launch_bounds__(256) ln_kernel(
    const float* __restrict__ x,
    const float* __restrict__ lw, const float* __restrict__ lb,
    float* __restrict__ out)
{
    int idx = blockIdx.x * 256 + threadIdx.x;       // float4 index
    int b = idx >> 18;                              // 262144 float4 per batch
    int r = idx & 262143;
    float2 st = g_stats[b];
    float4 z  = ((const float4*)g_z)[idx];
    float4 xv = ((const float4*)x)[idx];
    float4 w  = ((const float4*)lw)[r];
    float4 bb = ((const float4*)lb)[r];
    float4 o;
    o.x = (z.x - st.x) * st.y * w.x + bb.x + xv.x;
    o.y = (z.y - st.x) * st.y * w.y + bb.y + xv.y;
    o.z = (z.z - st.x) * st.y * w.z + bb.z + xv.z;
    o.w = (z.w - st.x) * st.y * w.w + bb.w + xv.w;
    ((float4*)out)[idx] = o;
}

// ============================================================================
extern "C" void kernel_launch(void* const* d_in, const int* in_sizes, int n_in,
                              void* d_out, int out_size)
{
    const float* x  = (const float*)d_in[0];
    const float* Wg = (const float*)d_in[1];
    const float* bg = (const float*)d_in[2];
    const float* Wt = (const float*)d_in[3];
    const float* bt = (const float*)d_in[4];
    const float* Wp = (const float*)d_in[5];
    const float* bp = (const float*)d_in[6];
    const float* Wz = (const float*)d_in[7];
    const float* bz = (const float*)d_in[8];
    const float* lw = (const float*)d_in[9];
    const float* lb = (const float*)d_in[10];
    float* out = (float*)d_out;

    cudaFuncSetAttribute(attn_kernel,  cudaFuncAttributeMaxDynamicSharedMemorySize, ATTN_SMEM);
    cudaFuncSetAttribute(zconv_kernel, cudaFuncAttributeMaxDynamicSharedMemorySize, ZCONV_SMEM);

    proj_kernel <<<dim3(NN / 64, 6, BB), 256>>>(x, Wt, bt, Wp, bp, Wg, bg);
    attn_kernel <<<dim3(NN / 64, BB), 256, ATTN_SMEM>>>();
    zconv_kernel<<<dim3(NN / 64, CC / 64, BB), 256, ZCONV_SMEM>>>(Wz, bz);
    stats_kernel<<<BB, 256>>>();
    ln_kernel   <<<(BB * CC * NN / 4) / 256, 256>>>(x, lw, lb, out);
}

// round 3
// speedup vs baseline: 3.1104x; 3.1104x over previous
#include <cuda_runtime.h>

// NonLocalBlock for GB300 (sm_103a).
// proj (FFMA 1x1conv GEMM) -> flash attention (tf32 mma.sync tensor cores)
// -> zconv(+LN partials) -> stats -> LN + residual.

#define BB 4
#define CC 256
#define FF 128
#define NN 4096
#define LN_EPS 1e-5f

typedef unsigned long long ull;

// ---- scratch (allocation-free: __device__ globals) ----
__device__ float g_theta[BB * NN * FF];   // Q rows [b][n][f]
__device__ float g_phi  [BB * NN * FF];   // K rows [b][n][f]
__device__ float g_gv   [BB * NN * FF];   // V rows [b][n][f]
__device__ float g_y    [BB * NN * FF];   // attn output [b][n][f]
__device__ float g_z    [BB * CC * NN];   // pre-LN z [b][c][n]
__device__ float2 g_part[BB * 256];       // per-tile (sum, sumsq)
__device__ float2 g_stats[BB];            // (mean, rstd)

// ---- packed fp32x2 helpers ----
__device__ __forceinline__ ull dup2(float x) {
    ull r; asm("mov.b64 %0, {%1, %1};" : "=l"(r) : "f"(x)); return r;
}
__device__ __forceinline__ ull fma2(ull a, ull b, ull c) {
    ull d; asm("fma.rn.f32x2 %0, %1, %2, %3;" : "=l"(d) : "l"(a), "l"(b), "l"(c)); return d;
}
__device__ __forceinline__ float2 upk(ull v) {
    float2 f; asm("mov.b64 {%0, %1}, %2;" : "=f"(f.x), "=f"(f.y) : "l"(v)); return f;
}

// ---- tf32 helpers ----
__device__ __forceinline__ unsigned f2tf32(float x) {
    unsigned u; asm("cvt.rna.tf32.f32 %0, %1;" : "=r"(u) : "f"(x)); return u;
}
__device__ __forceinline__ void mma_tf32(float* c, const unsigned* a, const unsigned* b) {
    asm volatile("mma.sync.aligned.m16n8k8.row.col.f32.tf32.tf32.f32 "
        "{%0,%1,%2,%3}, {%4,%5,%6,%7}, {%8,%9}, {%0,%1,%2,%3};"
        : "+f"(c[0]), "+f"(c[1]), "+f"(c[2]), "+f"(c[3])
        : "r"(a[0]), "r"(a[1]), "r"(a[2]), "r"(a[3]), "r"(b[0]), "r"(b[1]));
}

// ============================================================================
// proj: out[b,n,f] = sum_c x[b,c,n] * W[f,c] + bias[f]  (theta/phi/g)
// ============================================================================
__global__ void __launch_bounds__(256) proj_kernel(
    const float* __restrict__ x,
    const float* __restrict__ Wt, const float* __restrict__ bt,
    const float* __restrict__ Wp, const float* __restrict__ bp,
    const float* __restrict__ Wg, const float* __restrict__ bg)
{
    __shared__ __align__(16) float Xs[16][64];
    __shared__ __align__(16) float Ws[16][68];

    int b  = blockIdx.z;
    int p  = blockIdx.y >> 1;
    int f0 = (blockIdx.y & 1) * 64;
    int n0 = blockIdx.x * 64;

    const float* W; const float* bias; float* outp;
    if (p == 0)      { W = Wt; bias = bt; outp = g_theta; }
    else if (p == 1) { W = Wp; bias = bp; outp = g_phi;   }
    else             { W = Wg; bias = bg; outp = g_gv;    }

    int tid = threadIdx.x, tx = tid & 15, ty = tid >> 4;
    const float* xb = x + b * CC * NN;

    ull acc[4][2];
#pragma unroll
    for (int i = 0; i < 4; i++) { acc[i][0] = 0ULL; acc[i][1] = 0ULL; }

    for (int k0 = 0; k0 < CC; k0 += 16) {
#pragma unroll
        for (int i = 0; i < 4; i++) {
            int c = i * 4 + (tid >> 6);
            int n = tid & 63;
            Xs[c][n] = xb[(k0 + c) * NN + n0 + n];
        }
#pragma unroll
        for (int i = 0; i < 4; i++) {
            int f = i * 16 + (tid >> 4);
            int c = tid & 15;
            Ws[c][f] = W[(f0 + f) * CC + k0 + c];
        }
        __syncthreads();
#pragma unroll
        for (int k = 0; k < 16; k++) {
            float4 a = *(const float4*)&Xs[k][4 * ty];
            ulonglong2 w2 = *(const ulonglong2*)&Ws[k][4 * tx];
            ull a0 = dup2(a.x), a1 = dup2(a.y), a2 = dup2(a.z), a3 = dup2(a.w);
            acc[0][0] = fma2(a0, w2.x, acc[0][0]); acc[0][1] = fma2(a0, w2.y, acc[0][1]);
            acc[1][0] = fma2(a1, w2.x, acc[1][0]); acc[1][1] = fma2(a1, w2.y, acc[1][1]);
            acc[2][0] = fma2(a2, w2.x, acc[2][0]); acc[2][1] = fma2(a2, w2.y, acc[2][1]);
            acc[3][0] = fma2(a3, w2.x, acc[3][0]); acc[3][1] = fma2(a3, w2.y, acc[3][1]);
        }
        __syncthreads();
    }

    float b0 = bias[f0 + 4 * tx + 0], b1 = bias[f0 + 4 * tx + 1];
    float b2 = bias[f0 + 4 * tx + 2], b3 = bias[f0 + 4 * tx + 3];
#pragma unroll
    for (int i = 0; i < 4; i++) {
        float2 u0 = upk(acc[i][0]), u1 = upk(acc[i][1]);
        float4 w = make_float4(u0.x + b0, u0.y + b1, u1.x + b2, u1.y + b3);
        *(float4*)&outp[(b * NN + n0 + 4 * ty + i) * FF + f0 + 4 * tx] = w;
    }
}

// ============================================================================
// flash attention on tensor cores (tf32 mma.sync m16n8k8).
// CTA: 128 query rows, 8 warps (16 rows each -> softmax fully warp-local).
// Loop 64-key tiles: stage K,V (tf32) -> S=QK^T -> online softmax -> O+=PV.
// SMEM: Ks[64][132] u32, Vs[64][132] u32, Ps[128][68] u32  (= 100 KB)
// ============================================================================
#define KS_STRIDE 132
#define PS_STRIDE 68
#define ATTN_SMEM ((2 * 64 * KS_STRIDE + 128 * PS_STRIDE) * 4)

__global__ void __launch_bounds__(256, 1) attn_kernel()
{
    extern __shared__ __align__(16) unsigned smu[];
    unsigned* Ks = smu;                         // [64][132] tf32 (n, f)
    unsigned* Vs = smu + 64 * KS_STRIDE;        // [64][132] tf32 (n, f)
    unsigned* Ps = smu + 2 * 64 * KS_STRIDE;    // [128][68] tf32 (row, col)

    int b  = blockIdx.y;
    int n0 = blockIdx.x * 128;
    int tid  = threadIdx.x;
    int w    = tid >> 5;           // warp 0..7, owns rows 16w..16w+15
    int lane = tid & 31;
    int g    = lane >> 2;          // group 0..7
    int cq   = lane & 3;           // 0..3

    const float* Qg = g_theta + (b * NN + n0) * FF;
    const float* Kg = g_phi + b * NN * FF;
    const float* Vg = g_gv  + b * NN * FF;

    // ---- stage Q (tf32) through Ks/Vs, pull fragments to registers ----
    for (int i = tid; i < 128 * 32; i += 256) {           // 128 rows x 32 float4
        int r = i >> 5, c4 = (i & 31) * 4;
        float4 q = *(const float4*)&Qg[r * FF + c4];
        unsigned* dst = (r < 64 ? Ks : Vs) + (r & 63) * KS_STRIDE + c4;
        dst[0] = f2tf32(q.x); dst[1] = f2tf32(q.y);
        dst[2] = f2tf32(q.z); dst[3] = f2tf32(q.w);
    }
    __syncthreads();

    unsigned qf[16][4];            // A fragments, 16 k-steps
    {
        const unsigned* buf = (w < 4 ? Ks : Vs);
        int r0 = (16 * w + g) & 63;
#pragma unroll
        for (int k = 0; k < 16; k++) {
            qf[k][0] = buf[r0 * KS_STRIDE + 8 * k + cq];
            qf[k][1] = buf[(r0 + 8) * KS_STRIDE + 8 * k + cq];
            qf[k][2] = buf[r0 * KS_STRIDE + 8 * k + cq + 4];
            qf[k][3] = buf[(r0 + 8) * KS_STRIDE + 8 * k + cq + 4];
        }
    }

    float m0 = -3.0e38f, m1 = -3.0e38f, l0 = 0.0f, l1 = 0.0f;
    float oacc[16][4];
#pragma unroll
    for (int i = 0; i < 16; i++)
        oacc[i][0] = oacc[i][1] = oacc[i][2] = oacc[i][3] = 0.0f;

    unsigned* Pw = Ps + 16 * w * PS_STRIDE;    // warp-private P rows

    for (int t = 0; t < 64; t++) {
        const float* Kt = Kg + t * 64 * FF;
        const float* Vt = Vg + t * 64 * FF;
        __syncthreads();           // prior PV reads of Ks/Vs complete
        for (int i = tid; i < 64 * 32; i += 256) {
            int r = i >> 5, c4 = (i & 31) * 4;
            float4 kv = *(const float4*)&Kt[r * FF + c4];
            float4 vv = *(const float4*)&Vt[r * FF + c4];
            unsigned* dk = Ks + r * KS_STRIDE + c4;
            unsigned* dv = Vs + r * KS_STRIDE + c4;
            dk[0] = f2tf32(kv.x); dk[1] = f2tf32(kv.y);
            dk[2] = f2tf32(kv.z); dk[3] = f2tf32(kv.w);
            dv[0] = f2tf32(vv.x); dv[1] = f2tf32(vv.y);
            dv[2] = f2tf32(vv.z); dv[3] = f2tf32(vv.w);
        }
        __syncthreads();

        // ---- S = Q K^T : 8 n-tiles x 16 k-steps ----
        float sacc[8][4];
#pragma unroll
        for (int nt = 0; nt < 8; nt++)
            sacc[nt][0] = sacc[nt][1] = sacc[nt][2] = sacc[nt][3] = 0.0f;
#pragma unroll
        for (int nt = 0; nt < 8; nt++) {
            const unsigned* kb = Ks + (nt * 8 + g) * KS_STRIDE;
#pragma unroll
            for (int k = 0; k < 16; k++) {
                unsigned bf[2];
                bf[0] = kb[8 * k + cq];
                bf[1] = kb[8 * k + cq + 4];
                mma_tf32(sacc[nt], qf[k], bf);
            }
        }

        // ---- online softmax (rows g and g+8, warp-local) ----
        float mx0 = -3.0e38f, mx1 = -3.0e38f;
#pragma unroll
        for (int nt = 0; nt < 8; nt++) {
            mx0 = fmaxf(mx0, fmaxf(sacc[nt][0], sacc[nt][1]));
            mx1 = fmaxf(mx1, fmaxf(sacc[nt][2], sacc[nt][3]));
        }
        mx0 = fmaxf(mx0, __shfl_xor_sync(0xffffffffu, mx0, 1));
        mx0 = fmaxf(mx0, __shfl_xor_sync(0xffffffffu, mx0, 2));
        mx1 = fmaxf(mx1, __shfl_xor_sync(0xffffffffu, mx1, 1));
        mx1 = fmaxf(mx1, __shfl_xor_sync(0xffffffffu, mx1, 2));
        float mn0 = fmaxf(m0, mx0), mn1 = fmaxf(m1, mx1);
        float al0 = __expf(m0 - mn0), al1 = __expf(m1 - mn1);
        float su0 = 0.0f, su1 = 0.0f;
#pragma unroll
        for (int nt = 0; nt < 8; nt++) {
            float p00 = __expf(sacc[nt][0] - mn0);
            float p01 = __expf(sacc[nt][1] - mn0);
            float p10 = __expf(sacc[nt][2] - mn1);
            float p11 = __expf(sacc[nt][3] - mn1);
            su0 += p00 + p01; su1 += p10 + p11;
            int col = nt * 8 + 2 * cq;
            Pw[g * PS_STRIDE + col]           = f2tf32(p00);
            Pw[g * PS_STRIDE + col + 1]       = f2tf32(p01);
            Pw[(g + 8) * PS_STRIDE + col]     = f2tf32(p10);
            Pw[(g + 8) * PS_STRIDE + col + 1] = f2tf32(p11);
        }
        su0 += __shfl_xor_sync(0xffffffffu, su0, 1);
        su0 += __shfl_xor_sync(0xffffffffu, su0, 2);
        su1 += __shfl_xor_sync(0xffffffffu, su1, 1);
        su1 += __shfl_xor_sync(0xffffffffu, su1, 2);
        l0 = l0 * al0 + su0;  l1 = l1 * al1 + su1;
        m0 = mn0;             m1 = mn1;

        // rescale O by alpha
#pragma unroll
        for (int nt = 0; nt < 16; nt++) {
            oacc[nt][0] *= al0; oacc[nt][1] *= al0;
            oacc[nt][2] *= al1; oacc[nt][3] *= al1;
        }

        __syncwarp();          // P visible within warp

        // ---- P fragments (8 k-steps over 64 key cols) ----
        unsigned pf[8][4];
#pragma unroll
        for (int k = 0; k < 8; k++) {
            pf[k][0] = Pw[g * PS_STRIDE + 8 * k + cq];
            pf[k][1] = Pw[(g + 8) * PS_STRIDE + 8 * k + cq];
            pf[k][2] = Pw[g * PS_STRIDE + 8 * k + cq + 4];
            pf[k][3] = Pw[(g + 8) * PS_STRIDE + 8 * k + cq + 4];
        }

        // ---- O += P V : 16 n-tiles (128 f-cols) x 8 k-steps ----
#pragma unroll
        for (int nt = 0; nt < 16; nt++) {
#pragma unroll
            for (int k = 0; k < 8; k++) {
                unsigned bf[2];
                bf[0] = Vs[(8 * k + cq) * KS_STRIDE + nt * 8 + g];
                bf[1] = Vs[(8 * k + cq + 4) * KS_STRIDE + nt * 8 + g];
                mma_tf32(oacc[nt], pf[k], bf);
            }
        }
    }

    // ---- y = O / l ----
    float inv0 = 1.0f / l0, inv1 = 1.0f / l1;
    float* yb = g_y + (b * NN + n0) * FF;
    int r0 = 16 * w + g;
#pragma unroll
    for (int nt = 0; nt < 16; nt++) {
        int col = nt * 8 + 2 * cq;
        *(float2*)&yb[r0 * FF + col]       = make_float2(oacc[nt][0] * inv0, oacc[nt][1] * inv0);
        *(float2*)&yb[(r0 + 8) * FF + col] = make_float2(oacc[nt][2] * inv1, oacc[nt][3] * inv1);
    }
}

// ============================================================================
// zconv: z[b,c,n] = sum_f Wz[c,f] * y[b,n,f] + bz[c]; per-tile LN partials.
// ============================================================================
#define ZCONV_SMEM (2 * 128 * 68 * 4)

__global__ void __launch_bounds__(256) zconv_kernel(
    const float* __restrict__ Wz, const float* __restrict__ bz)
{
    extern __shared__ __align__(16) float sm[];
    float* WzT = sm;
    float* YsT = sm + 128 * 68;

    int b  = blockIdx.z;
    int c0 = blockIdx.y * 64;
    int n0 = blockIdx.x * 64;
    int tid = threadIdx.x, tx = tid & 15, ty = tid >> 4;

    const float* yb = g_y + b * NN * FF;
    for (int i = tid; i < 64 * FF; i += 256) {
        int c = i >> 7, f = i & 127;
        WzT[f * 68 + c] = Wz[(c0 + c) * FF + f];
    }
    for (int i = tid; i < 64 * FF; i += 256) {
        int n = i >> 7, f = i & 127;
        YsT[f * 68 + n] = yb[(n0 + n) * FF + f];
    }
    __syncthreads();

    ull acc[4][2];
#pragma unroll
    for (int i = 0; i < 4; i++) { acc[i][0] = 0ULL; acc[i][1] = 0ULL; }
#pragma unroll 8
    for (int k = 0; k < FF; k++) {
        float4 a = *(const float4*)&WzT[k * 68 + 4 * ty];
        ulonglong2 yv = *(const ulonglong2*)&YsT[k * 68 + 4 * tx];
        ull a0 = dup2(a.x), a1 = dup2(a.y), a2 = dup2(a.z), a3 = dup2(a.w);
        acc[0][0] = fma2(a0, yv.x, acc[0][0]); acc[0][1] = fma2(a0, yv.y, acc[0][1]);
        acc[1][0] = fma2(a1, yv.x, acc[1][0]); acc[1][1] = fma2(a1, yv.y, acc[1][1]);
        acc[2][0] = fma2(a2, yv.x, acc[2][0]); acc[2][1] = fma2(a2, yv.y, acc[2][1]);
        acc[3][0] = fma2(a3, yv.x, acc[3][0]); acc[3][1] = fma2(a3, yv.y, acc[3][1]);
    }

    float lsum = 0.0f, lsq = 0.0f;
    float* zb = g_z + b * CC * NN;
#pragma unroll
    for (int i = 0; i < 4; i++) {
        float bzv = bz[c0 + 4 * ty + i];
        float2 u0 = upk(acc[i][0]), u1 = upk(acc[i][1]);
        float z0 = u0.x + bzv, z1 = u0.y + bzv, z2 = u1.x + bzv, z3 = u1.y + bzv;
        *(float4*)&zb[(c0 + 4 * ty + i) * NN + n0 + 4 * tx] = make_float4(z0, z1, z2, z3);
        lsum += z0 + z1 + z2 + z3;
        lsq  += z0 * z0 + z1 * z1 + z2 * z2 + z3 * z3;
    }

    __syncthreads();
    float* rs = sm;
    float* rq = sm + 256;
    rs[tid] = lsum; rq[tid] = lsq;
    __syncthreads();
#pragma unroll
    for (int s = 128; s > 0; s >>= 1) {
        if (tid < s) { rs[tid] += rs[tid + s]; rq[tid] += rq[tid + s]; }
        __syncthreads();
    }
    if (tid == 0)
        g_part[b * 256 + blockIdx.y * 64 + blockIdx.x] = make_float2(rs[0], rq[0]);
}

// ============================================================================
__global__ void stats_kernel()
{
    __shared__ float rs[256], rq[256];
    int b = blockIdx.x, tid = threadIdx.x;
    float2 v = g_part[b * 256 + tid];
    rs[tid] = v.x; rq[tid] = v.y;
    __syncthreads();
#pragma unroll
    for (int s = 128; s > 0; s >>= 1) {
        if (tid < s) { rs[tid] += rs[tid + s]; rq[tid] += rq[tid + s]; }
        __syncthreads();
    }
    if (tid == 0) {
        float inv  = 1.0f / (float)(CC * NN);
        float mean = rs[0] * inv;
        float var  = rq[0] * inv - mean * mean;
        g_stats[b] = make_float2(mean, rsqrtf(var + LN_EPS));
    }
}

// ============================================================================
__global__ void __launch_bounds__(256) ln_kernel(
    const float* __restrict__ x,
    const float* __restrict__ lw, const float* __restrict__ lb,
    float* __restrict__ out)
{
    int idx = blockIdx.x * 256 + threadIdx.x;
    int b = idx >> 18;
    int r = idx & 262143;
    float2 st = g_stats[b];
    float4 z  = ((const float4*)g_z)[idx];
    float4 xv = ((const float4*)x)[idx];
    float4 w  = ((const float4*)lw)[r];
    float4 bb = ((const float4*)lb)[r];
    float4 o;
    o.x = (z.x - st.x) * st.y * w.x + bb.x + xv.x;
    o.y = (z.y - st.x) * st.y * w.y + bb.y + xv.y;
    o.z = (z.z - st.x) * st.y * w.z + bb.z + xv.z;
    o.w = (z.w - st.x) * st.y * w.w + bb.w + xv.w;
    ((float4*)out)[idx] = o;
}

// ============================================================================
extern "C" void kernel_launch(void* const* d_in, const int* in_sizes, int n_in,
                              void* d_out, int out_size)
{
    const float* x  = (const float*)d_in[0];
    const float* Wg = (const float*)d_in[1];
    const float* bg = (const float*)d_in[2];
    const float* Wt = (const float*)d_in[3];
    const float* bt = (const float*)d_in[4];
    const float* Wp = (const float*)d_in[5];
    const float* bp = (const float*)d_in[6];
    const float* Wz = (const float*)d_in[7];
    const float* bz = (const float*)d_in[8];
    const float* lw = (const float*)d_in[9];
    const float* lb = (const float*)d_in[10];
    float* out = (float*)d_out;

    cudaFuncSetAttribute(attn_kernel,  cudaFuncAttributeMaxDynamicSharedMemorySize, ATTN_SMEM);
    cudaFuncSetAttribute(zconv_kernel, cudaFuncAttributeMaxDynamicSharedMemorySize, ZCONV_SMEM);

    proj_kernel <<<dim3(NN / 64, 6, BB), 256>>>(x, Wt, bt, Wp, bp, Wg, bg);
    attn_kernel <<<dim3(NN / 128, BB), 256, ATTN_SMEM>>>();
    zconv_kernel<<<dim3(NN / 64, CC / 64, BB), 256, ZCONV_SMEM>>>(Wz, bz);
    stats_kernel<<<BB, 256>>>();
    ln_kernel   <<<(BB * CC * NN / 4) / 256, 256>>>(x, lw, lb, out);
}

// round 7
// speedup vs baseline: 3.8362x; 1.2333x over previous
#include <cuda_runtime.h>

// NonLocalBlock for GB300 (sm_103a), round 4.
// proj (FFMA GEMM, writes tf32 MMA-fragment-ordered Q/K/V) ->
// flash attention (tf32 mma.sync, cp.async double-buffered, vectorized frags) ->
// zconv(+LN partials) -> stats -> LN + residual.

#define BB 4
#define CC 256
#define FF 128
#define NN 4096
#define LN_EPS 1e-5f

typedef unsigned long long ull;

// ---- scratch ----
__device__ unsigned g_Qp[BB * 256 * 16 * 128];  // A-frag order  (8 MB)
__device__ unsigned g_Kp[BB * 64 * 8 * 8 * 128];  // B-frag order (8 MB)
__device__ unsigned g_Vp[BB * 64 * 16 * 4 * 128]; // B-frag order (8 MB)
__device__ float g_y [BB * NN * FF];
__device__ float g_z [BB * CC * NN];
__device__ float2 g_part[BB * 256];
__device__ float2 g_stats[BB];

// ---- packed fp32x2 helpers ----
__device__ __forceinline__ ull dup2(float x) {
    ull r; asm("mov.b64 %0, {%1, %1};" : "=l"(r) : "f"(x)); return r;
}
__device__ __forceinline__ ull fma2(ull a, ull b, ull c) {
    ull d; asm("fma.rn.f32x2 %0, %1, %2, %3;" : "=l"(d) : "l"(a), "l"(b), "l"(c)); return d;
}
__device__ __forceinline__ float2 upk(ull v) {
    float2 f; asm("mov.b64 {%0, %1}, %2;" : "=f"(f.x), "=f"(f.y) : "l"(v)); return f;
}

// ---- tf32 / mma helpers ----
__device__ __forceinline__ unsigned f2tf32(float x) {
    unsigned u; asm("cvt.rna.tf32.f32 %0, %1;" : "=r"(u) : "f"(x)); return u;
}
__device__ __forceinline__ ull pack2(unsigned lo, unsigned hi) {
    ull r; asm("mov.b64 %0, {%1, %2};" : "=l"(r) : "r"(lo), "r"(hi)); return r;
}
__device__ __forceinline__ void mma_tf32(float* c, const unsigned* a, unsigned b0, unsigned b1) {
    asm volatile("mma.sync.aligned.m16n8k8.row.col.f32.tf32.tf32.f32 "
        "{%0,%1,%2,%3}, {%4,%5,%6,%7}, {%8,%9}, {%0,%1,%2,%3};"
        : "+f"(c[0]), "+f"(c[1]), "+f"(c[2]), "+f"(c[3])
        : "r"(a[0]), "r"(a[1]), "r"(a[2]), "r"(a[3]), "r"(b0), "r"(b1));
}

// ---- fragment-order addressing (u32 element index) ----
__device__ __forceinline__ unsigned qp_addr(int b, int n, int f) {
    int wt = n >> 4, k = f >> 3;
    int lane = ((n & 7) << 2) + (f & 3);
    int sel  = (((f >> 2) & 1) << 1) + ((n >> 3) & 1);
    return ((((b << 8) + wt) << 4) + k) * 128 + (lane << 2) + sel;
}
__device__ __forceinline__ unsigned kp_addr(int b, int key, int f) {
    int kt = key >> 6, nt = (key & 63) >> 3;
    int kblk = f >> 3, kpair = kblk >> 1, which = kblk & 1;
    int lane = ((key & 7) << 2) + (f & 3), half = (f >> 2) & 1;
    return ((((b << 6) + kt) * 8 + nt) * 8 + kpair) * 128 + (lane << 2) + (which << 1) + half;
}
__device__ __forceinline__ unsigned vp_addr(int b, int key, int f) {
    int kt = key >> 6, nt = f >> 3;
    int kblk = (key & 63) >> 3, kpair = kblk >> 1, which = kblk & 1;
    int lane = ((f & 7) << 2) + (key & 3), half = (key >> 2) & 1;
    return ((((b << 6) + kt) * 16 + nt) * 4 + kpair) * 128 + (lane << 2) + (which << 1) + half;
}

// ---- cp.async ----
__device__ __forceinline__ void cp16(unsigned smem_addr, const void* gptr) {
    asm volatile("cp.async.cg.shared.global [%0], [%1], 16;" :: "r"(smem_addr), "l"(gptr));
}

// ============================================================================
// proj: out[b,n,f] = sum_c x[b,c,n] * W[f,c] + bias[f]; store tf32 frag-ordered.
// ============================================================================
__global__ void __launch_bounds__(256) proj_kernel(
    const float* __restrict__ x,
    const float* __restrict__ Wt, const float* __restrict__ bt,
    const float* __restrict__ Wp, const float* __restrict__ bp,
    const float* __restrict__ Wg, const float* __restrict__ bg)
{
    __shared__ __align__(16) float Xs[16][64];
    __shared__ __align__(16) float Ws[16][68];

    int b  = blockIdx.z;
    int p  = blockIdx.y >> 1;
    int f0 = (blockIdx.y & 1) * 64;
    int n0 = blockIdx.x * 64;

    const float* W; const float* bias;
    if (p == 0)      { W = Wt; bias = bt; }
    else if (p == 1) { W = Wp; bias = bp; }
    else             { W = Wg; bias = bg; }

    int tid = threadIdx.x, tx = tid & 15, ty = tid >> 4;
    const float* xb = x + b * CC * NN;

    ull acc[4][2];
#pragma unroll
    for (int i = 0; i < 4; i++) { acc[i][0] = 0ULL; acc[i][1] = 0ULL; }

    for (int k0 = 0; k0 < CC; k0 += 16) {
#pragma unroll
        for (int i = 0; i < 4; i++) {
            int c = i * 4 + (tid >> 6);
            int n = tid & 63;
            Xs[c][n] = xb[(k0 + c) * NN + n0 + n];
        }
#pragma unroll
        for (int i = 0; i < 4; i++) {
            int f = i * 16 + (tid >> 4);
            int c = tid & 15;
            Ws[c][f] = W[(f0 + f) * CC + k0 + c];
        }
        __syncthreads();
#pragma unroll
        for (int k = 0; k < 16; k++) {
            float4 a = *(const float4*)&Xs[k][4 * ty];
            ulonglong2 w2 = *(const ulonglong2*)&Ws[k][4 * tx];
            ull a0 = dup2(a.x), a1 = dup2(a.y), a2 = dup2(a.z), a3 = dup2(a.w);
            acc[0][0] = fma2(a0, w2.x, acc[0][0]); acc[0][1] = fma2(a0, w2.y, acc[0][1]);
            acc[1][0] = fma2(a1, w2.x, acc[1][0]); acc[1][1] = fma2(a1, w2.y, acc[1][1]);
            acc[2][0] = fma2(a2, w2.x, acc[2][0]); acc[2][1] = fma2(a2, w2.y, acc[2][1]);
            acc[3][0] = fma2(a3, w2.x, acc[3][0]); acc[3][1] = fma2(a3, w2.y, acc[3][1]);
        }
        __syncthreads();
    }

    float bv[4];
#pragma unroll
    for (int j = 0; j < 4; j++) bv[j] = bias[f0 + 4 * tx + j];

#pragma unroll
    for (int i = 0; i < 4; i++) {
        int n = n0 + 4 * ty + i;
        float2 u0 = upk(acc[i][0]), u1 = upk(acc[i][1]);
        float v[4] = { u0.x + bv[0], u0.y + bv[1], u1.x + bv[2], u1.y + bv[3] };
#pragma unroll
        for (int j = 0; j < 4; j++) {
            int f = f0 + 4 * tx + j;
            unsigned t = f2tf32(v[j]);
            if (p == 0)      g_Qp[qp_addr(b, n, f)] = t;
            else if (p == 1) g_Kp[kp_addr(b, n, f)] = t;
            else             g_Vp[vp_addr(b, n, f)] = t;
        }
    }
}

// ============================================================================
// flash attention: 128 q-rows/CTA, 8 warps, cp.async double-buffered K/V tiles
// in fragment order; vectorized 16B B-frag loads; packed 64-bit P round-trip.
// SMEM: 2 x (Kp 32KB + Vp 32KB) + Pp 32KB = 160 KB
// ============================================================================
#define ATTN_SMEM (20480 * 8)

__global__ void __launch_bounds__(256, 1) attn_kernel()
{
    extern __shared__ __align__(16) ull sm8[];
    // layout: [buf0: K 4096 | V 4096][buf1: K 4096 | V 4096][Pp 4096]

    int b  = blockIdx.y;
    int qt = blockIdx.x;
    int tid  = threadIdx.x;
    int w    = tid >> 5;
    int lane = tid & 31;
    int g    = lane >> 2;
    int cq   = lane & 3;

    // ---- Q fragments straight from global (A-frag order, coalesced v4) ----
    unsigned qf[16][4];
    {
        const uint4* qsrc = (const uint4*)&g_Qp[(((b << 8) + qt * 8 + w) << 4) * 128];
#pragma unroll
        for (int k = 0; k < 16; k++) {
            uint4 q = __ldg(&qsrc[k * 32 + lane]);
            qf[k][0] = q.x; qf[k][1] = q.y; qf[k][2] = q.z; qf[k][3] = q.w;
        }
    }

    float m0 = -3.0e38f, m1 = -3.0e38f, l0 = 0.0f, l1 = 0.0f;
    float oacc[16][4];
#pragma unroll
    for (int i = 0; i < 16; i++)
        oacc[i][0] = oacc[i][1] = oacc[i][2] = oacc[i][3] = 0.0f;

    ull* Pw = sm8 + 16384 + w * 512;   // warp-private: [64 cols][8 g]

    const ull* gk_base = (const ull*)g_Kp + (size_t)b * 64 * 4096;
    const ull* gv_base = (const ull*)g_Vp + (size_t)b * 64 * 4096;
    unsigned sm_base_u32 = (unsigned)__cvta_generic_to_shared(sm8);

    // prologue: stage tile 0 into buf 0
    {
        const ull* gk = gk_base;
        const ull* gv = gv_base;
#pragma unroll
        for (int i = 0; i < 8; i++) {
            int idx = tid + i * 256;               // 16B chunk index (2048 per tile)
            cp16(sm_base_u32 + idx * 16, gk + idx * 2);
            cp16(sm_base_u32 + (4096 + idx * 2) * 8, gv + idx * 2);
        }
        asm volatile("cp.async.commit_group;" ::: "memory");
    }

    for (int t = 0; t < 64; t++) {
        __syncthreads();   // all reads of the buffer being overwritten are done
        if (t + 1 < 64) {
            int s = (t + 1) & 1;
            const ull* gk = gk_base + (t + 1) * 4096;
            const ull* gv = gv_base + (t + 1) * 4096;
            unsigned kb = sm_base_u32 + s * 8192 * 8;
#pragma unroll
            for (int i = 0; i < 8; i++) {
                int idx = tid + i * 256;
                cp16(kb + idx * 16, gk + idx * 2);
                cp16(kb + (4096 + idx * 2) * 8, gv + idx * 2);
            }
            asm volatile("cp.async.commit_group;" ::: "memory");
            asm volatile("cp.async.wait_group 1;" ::: "memory");
        } else {
            asm volatile("cp.async.wait_group 0;" ::: "memory");
        }
        __syncthreads();

        const ull* Ksm = sm8 + (t & 1) * 8192;
        const ull* Vsm = Ksm + 4096;

        // ---- S = Q K^T : 8 key-tiles x 16 k-steps (2 per 16B load) ----
        float sacc[8][4];
#pragma unroll
        for (int nt = 0; nt < 8; nt++)
            sacc[nt][0] = sacc[nt][1] = sacc[nt][2] = sacc[nt][3] = 0.0f;
#pragma unroll
        for (int nt = 0; nt < 8; nt++) {
#pragma unroll
            for (int kp = 0; kp < 8; kp++) {
                uint4 kk = *(const uint4*)&Ksm[(nt * 8 + kp) * 64 + lane * 2];
                mma_tf32(sacc[nt], qf[2 * kp],     kk.x, kk.y);
                mma_tf32(sacc[nt], qf[2 * kp + 1], kk.z, kk.w);
            }
        }

        // ---- online softmax (rows g, g+8; warp-local) ----
        float mx0 = -3.0e38f, mx1 = -3.0e38f;
#pragma unroll
        for (int nt = 0; nt < 8; nt++) {
            mx0 = fmaxf(mx0, fmaxf(sacc[nt][0], sacc[nt][1]));
            mx1 = fmaxf(mx1, fmaxf(sacc[nt][2], sacc[nt][3]));
        }
        mx0 = fmaxf(mx0, __shfl_xor_sync(0xffffffffu, mx0, 1));
        mx0 = fmaxf(mx0, __shfl_xor_sync(0xffffffffu, mx0, 2));
        mx1 = fmaxf(mx1, __shfl_xor_sync(0xffffffffu, mx1, 1));
        mx1 = fmaxf(mx1, __shfl_xor_sync(0xffffffffu, mx1, 2));
        float mn0 = fmaxf(m0, mx0), mn1 = fmaxf(m1, mx1);
        float al0 = __expf(m0 - mn0), al1 = __expf(m1 - mn1);
        float su0 = 0.0f, su1 = 0.0f;
#pragma unroll
        for (int nt = 0; nt < 8; nt++) {
            float p00 = __expf(sacc[nt][0] - mn0);
            float p01 = __expf(sacc[nt][1] - mn0);
            float p10 = __expf(sacc[nt][2] - mn1);
            float p11 = __expf(sacc[nt][3] - mn1);
            su0 += p00 + p01; su1 += p10 + p11;
            Pw[(nt * 8 + 2 * cq) * 8 + g]     = pack2(f2tf32(p00), f2tf32(p10));
            Pw[(nt * 8 + 2 * cq + 1) * 8 + g] = pack2(f2tf32(p01), f2tf32(p11));
        }
        su0 += __shfl_xor_sync(0xffffffffu, su0, 1);
        su0 += __shfl_xor_sync(0xffffffffu, su0, 2);
        su1 += __shfl_xor_sync(0xffffffffu, su1, 1);
        su1 += __shfl_xor_sync(0xffffffffu, su1, 2);
        l0 = l0 * al0 + su0;  l1 = l1 * al1 + su1;
        m0 = mn0;             m1 = mn1;

#pragma unroll
        for (int nt = 0; nt < 16; nt++) {
            oacc[nt][0] *= al0; oacc[nt][1] *= al0;
            oacc[nt][2] *= al1; oacc[nt][3] *= al1;
        }

        __syncwarp();

        // ---- P fragments (packed 64-bit reads) ----
        unsigned pf[8][4];
#pragma unroll
        for (int k = 0; k < 8; k++) {
            uint2 u = *(const uint2*)&Pw[(8 * k + cq) * 8 + g];
            uint2 v = *(const uint2*)&Pw[(8 * k + cq + 4) * 8 + g];
            pf[k][0] = u.x; pf[k][1] = u.y; pf[k][2] = v.x; pf[k][3] = v.y;
        }

        // ---- O += P V : 16 f-tiles x 8 k-steps (2 per 16B load) ----
#pragma unroll
        for (int nt = 0; nt < 16; nt++) {
#pragma unroll
            for (int kp = 0; kp < 4; kp++) {
                uint4 vv = *(const uint4*)&Vsm[(nt * 4 + kp) * 64 + lane * 2];
                mma_tf32(oacc[nt], pf[2 * kp],     vv.x, vv.y);
                mma_tf32(oacc[nt], pf[2 * kp + 1], vv.z, vv.w);
            }
        }
    }

    // ---- y = O / l ----
    float inv0 = 1.0f / l0, inv1 = 1.0f / l1;
    float* yb = g_y + (b * NN + qt * 128) * FF;
    int r0 = 16 * w + g;
#pragma unroll
    for (int nt = 0; nt < 16; nt++) {
        int col = nt * 8 + 2 * cq;
        *(float2*)&yb[r0 * FF + col]       = make_float2(oacc[nt][0] * inv0, oacc[nt][1] * inv0);
        *(float2*)&yb[(r0 + 8) * FF + col] = make_float2(oacc[nt][2] * inv1, oacc[nt][3] * inv1);
    }
}

// ============================================================================
// zconv: z[b,c,n] = sum_f Wz[c,f] * y[b,n,f] + bz[c]; per-tile LN partials.
// ============================================================================
#define ZCONV_SMEM (2 * 128 * 68 * 4)

__global__ void __launch_bounds__(256) zconv_kernel(
    const float* __restrict__ Wz, const float* __restrict__ bz)
{
    extern __shared__ __align__(16) float sm[];
    float* WzT = sm;
    float* YsT = sm + 128 * 68;

    int b  = blockIdx.z;
    int c0 = blockIdx.y * 64;
    int n0 = blockIdx.x * 64;
    int tid = threadIdx.x, tx = tid & 15, ty = tid >> 4;

    const float* yb = g_y + b * NN * FF;
    for (int i = tid; i < 64 * FF; i += 256) {
        int c = i >> 7, f = i & 127;
        WzT[f * 68 + c] = Wz[(c0 + c) * FF + f];
    }
    for (int i = tid; i < 64 * FF; i += 256) {
        int n = i >> 7, f = i & 127;
        YsT[f * 68 + n] = yb[(n0 + n) * FF + f];
    }
    __syncthreads();

    ull acc[4][2];
#pragma unroll
    for (int i = 0; i < 4; i++) { acc[i][0] = 0ULL; acc[i][1] = 0ULL; }
#pragma unroll 8
    for (int k = 0; k < FF; k++) {
        float4 a = *(const float4*)&WzT[k * 68 + 4 * ty];
        ulonglong2 yv = *(const ulonglong2*)&YsT[k * 68 + 4 * tx];
        ull a0 = dup2(a.x), a1 = dup2(a.y), a2 = dup2(a.z), a3 = dup2(a.w);
        acc[0][0] = fma2(a0, yv.x, acc[0][0]); acc[0][1] = fma2(a0, yv.y, acc[0][1]);
        acc[1][0] = fma2(a1, yv.x, acc[1][0]); acc[1][1] = fma2(a1, yv.y, acc[1][1]);
        acc[2][0] = fma2(a2, yv.x, acc[2][0]); acc[2][1] = fma2(a2, yv.y, acc[2][1]);
        acc[3][0] = fma2(a3, yv.x, acc[3][0]); acc[3][1] = fma2(a3, yv.y, acc[3][1]);
    }

    float lsum = 0.0f, lsq = 0.0f;
    float* zb = g_z + b * CC * NN;
#pragma unroll
    for (int i = 0; i < 4; i++) {
        float bzv = bz[c0 + 4 * ty + i];
        float2 u0 = upk(acc[i][0]), u1 = upk(acc[i][1]);
        float z0 = u0.x + bzv, z1 = u0.y + bzv, z2 = u1.x + bzv, z3 = u1.y + bzv;
        *(float4*)&zb[(c0 + 4 * ty + i) * NN + n0 + 4 * tx] = make_float4(z0, z1, z2, z3);
        lsum += z0 + z1 + z2 + z3;
        lsq  += z0 * z0 + z1 * z1 + z2 * z2 + z3 * z3;
    }

    __syncthreads();
    float* rs = sm;
    float* rq = sm + 256;
    rs[tid] = lsum; rq[tid] = lsq;
    __syncthreads();
#pragma unroll
    for (int s = 128; s > 0; s >>= 1) {
        if (tid < s) { rs[tid] += rs[tid + s]; rq[tid] += rq[tid + s]; }
        __syncthreads();
    }
    if (tid == 0)
        g_part[b * 256 + blockIdx.y * 64 + blockIdx.x] = make_float2(rs[0], rq[0]);
}

// ============================================================================
__global__ void stats_kernel()
{
    __shared__ float rs[256], rq[256];
    int b = blockIdx.x, tid = threadIdx.x;
    float2 v = g_part[b * 256 + tid];
    rs[tid] = v.x; rq[tid] = v.y;
    __syncthreads();
#pragma unroll
    for (int s = 128; s > 0; s >>= 1) {
        if (tid < s) { rs[tid] += rs[tid + s]; rq[tid] += rq[tid + s]; }
        __syncthreads();
    }
    if (tid == 0) {
        float inv  = 1.0f / (float)(CC * NN);
        float mean = rs[0] * inv;
        float var  = rq[0] * inv - mean * mean;
        g_stats[b] = make_float2(mean, rsqrtf(var + LN_EPS));
    }
}

// ============================================================================
__global__ void __launch_bounds__(256) ln_kernel(
    const float* __restrict__ x,
    const float* __restrict__ lw, const float* __restrict__ lb,
    float* __restrict__ out)
{
    int idx = blockIdx.x * 256 + threadIdx.x;
    int b = idx >> 18;
    int r = idx & 262143;
    float2 st = g_stats[b];
    float4 z  = ((const float4*)g_z)[idx];
    float4 xv = ((const float4*)x)[idx];
    float4 w  = ((const float4*)lw)[r];
    float4 bb = ((const float4*)lb)[r];
    float4 o;
    o.x = (z.x - st.x) * st.y * w.x + bb.x + xv.x;
    o.y = (z.y - st.x) * st.y * w.y + bb.y + xv.y;
    o.z = (z.z - st.x) * st.y * w.z + bb.z + xv.z;
    o.w = (z.w - st.x) * st.y * w.w + bb.w + xv.w;
    ((float4*)out)[idx] = o;
}

// ============================================================================
extern "C" void kernel_launch(void* const* d_in, const int* in_sizes, int n_in,
                              void* d_out, int out_size)
{
    const float* x  = (const float*)d_in[0];
    const float* Wg = (const float*)d_in[1];
    const float* bg = (const float*)d_in[2];
    const float* Wt = (const float*)d_in[3];
    const float* bt = (const float*)d_in[4];
    const float* Wp = (const float*)d_in[5];
    const float* bp = (const float*)d_in[6];
    const float* Wz = (const float*)d_in[7];
    const float* bz = (const float*)d_in[8];
    const float* lw = (const float*)d_in[9];
    const float* lb = (const float*)d_in[10];
    float* out = (float*)d_out;

    cudaFuncSetAttribute(attn_kernel,  cudaFuncAttributeMaxDynamicSharedMemorySize, ATTN_SMEM);
    cudaFuncSetAttribute(zconv_kernel, cudaFuncAttributeMaxDynamicSharedMemorySize, ZCONV_SMEM);

    proj_kernel <<<dim3(NN / 64, 6, BB), 256>>>(x, Wt, bt, Wp, bp, Wg, bg);
    attn_kernel <<<dim3(NN / 128, BB), 256, ATTN_SMEM>>>();
    zconv_kernel<<<dim3(NN / 64, CC / 64, BB), 256, ZCONV_SMEM>>>(Wz, bz);
    stats_kernel<<<BB, 256>>>();
    ln_kernel   <<<(BB * CC * NN / 4) / 256, 256>>>(x, lw, lb, out);
}

// round 11
// speedup vs baseline: 6.0000x; 1.5641x over previous
#include <cuda_runtime.h>

// NonLocalBlock for GB300 (sm_103a), round 8.
// proj (FFMA fp32 GEMM, writes bf16 m16n8k16-fragment-ordered Q/K/V) ->
// flash attention (bf16 mma.sync m16n8k16, cp.async double-buffered,
//                  P re-fragmented in registers: NO smem round-trip) ->
// zconv(+LN partials) -> stats -> LN + residual.

#define BB 4
#define CC 256
#define FF 128
#define NN 4096
#define LN_EPS 1e-5f

typedef unsigned long long ull;

// ---- scratch ----
__device__ unsigned g_Qp[BB * 256 * 8 * 32 * 4];   // A-frag order (4 MB)
__device__ unsigned g_Kp[BB * 64 * 8 * 4 * 32 * 4]; // B-frag order (4 MB)
__device__ unsigned g_Vp[BB * 64 * 16 * 2 * 32 * 4];// B-frag order (4 MB)
__device__ float g_y [BB * NN * FF];
__device__ float g_z [BB * CC * NN];
__device__ float2 g_part[BB * 256];
__device__ float2 g_stats[BB];

// ---- packed fp32x2 helpers ----
__device__ __forceinline__ ull dup2(float x) {
    ull r; asm("mov.b64 %0, {%1, %1};" : "=l"(r) : "f"(x)); return r;
}
__device__ __forceinline__ ull fma2(ull a, ull b, ull c) {
    ull d; asm("fma.rn.f32x2 %0, %1, %2, %3;" : "=l"(d) : "l"(a), "l"(b), "l"(c)); return d;
}
__device__ __forceinline__ float2 upk(ull v) {
    float2 f; asm("mov.b64 {%0, %1}, %2;" : "=f"(f.x), "=f"(f.y) : "l"(v)); return f;
}

// ---- bf16 / mma helpers ----
// pack (lo, hi) -> u32 bf16x2, lo in bits[0:16)
__device__ __forceinline__ unsigned pbf(float lo, float hi) {
    unsigned r; asm("cvt.rn.bf16x2.f32 %0, %1, %2;" : "=r"(r) : "f"(hi), "f"(lo));
    return r;
}
__device__ __forceinline__ void mma_bf16(float* c, const unsigned* a, unsigned b0, unsigned b1) {
    asm volatile("mma.sync.aligned.m16n8k16.row.col.f32.bf16.bf16.f32 "
        "{%0,%1,%2,%3}, {%4,%5,%6,%7}, {%8,%9}, {%0,%1,%2,%3};"
        : "+f"(c[0]), "+f"(c[1]), "+f"(c[2]), "+f"(c[3])
        : "r"(a[0]), "r"(a[1]), "r"(a[2]), "r"(a[3]), "r"(b0), "r"(b1));
}

// ---- cp.async ----
__device__ __forceinline__ void cp16(unsigned smem_addr, const void* gptr) {
    asm volatile("cp.async.cg.shared.global [%0], [%1], 16;" :: "r"(smem_addr), "l"(gptr));
}

// ============================================================================
// proj: out[b,n,f] = sum_c x[b,c,n] * W[f,c] + bias[f];
// store as bf16 m16n8k16 fragments (Qp: A-order; Kp, Vp: B-order).
// ============================================================================
__global__ void __launch_bounds__(256) proj_kernel(
    const float* __restrict__ x,
    const float* __restrict__ Wt, const float* __restrict__ bt,
    const float* __restrict__ Wp, const float* __restrict__ bp,
    const float* __restrict__ Wg, const float* __restrict__ bg)
{
    __shared__ __align__(16) float Xs[16][64];
    __shared__ __align__(16) float Ws[16][68];

    int b  = blockIdx.z;
    int p  = blockIdx.y >> 1;
    int f0 = (blockIdx.y & 1) * 64;
    int n0 = blockIdx.x * 64;

    const float* W; const float* bias;
    if (p == 0)      { W = Wt; bias = bt; }
    else if (p == 1) { W = Wp; bias = bp; }
    else             { W = Wg; bias = bg; }

    int tid = threadIdx.x, tx = tid & 15, ty = tid >> 4;
    const float* xb = x + b * CC * NN;

    ull acc[4][2];
#pragma unroll
    for (int i = 0; i < 4; i++) { acc[i][0] = 0ULL; acc[i][1] = 0ULL; }

    for (int k0 = 0; k0 < CC; k0 += 16) {
#pragma unroll
        for (int i = 0; i < 4; i++) {
            int c = i * 4 + (tid >> 6);
            int n = tid & 63;
            Xs[c][n] = xb[(k0 + c) * NN + n0 + n];
        }
#pragma unroll
        for (int i = 0; i < 4; i++) {
            int f = i * 16 + (tid >> 4);
            int c = tid & 15;
            Ws[c][f] = W[(f0 + f) * CC + k0 + c];
        }
        __syncthreads();
#pragma unroll
        for (int k = 0; k < 16; k++) {
            float4 a = *(const float4*)&Xs[k][4 * ty];
            ulonglong2 w2 = *(const ulonglong2*)&Ws[k][4 * tx];
            ull a0 = dup2(a.x), a1 = dup2(a.y), a2 = dup2(a.z), a3 = dup2(a.w);
            acc[0][0] = fma2(a0, w2.x, acc[0][0]); acc[0][1] = fma2(a0, w2.y, acc[0][1]);
            acc[1][0] = fma2(a1, w2.x, acc[1][0]); acc[1][1] = fma2(a1, w2.y, acc[1][1]);
            acc[2][0] = fma2(a2, w2.x, acc[2][0]); acc[2][1] = fma2(a2, w2.y, acc[2][1]);
            acc[3][0] = fma2(a3, w2.x, acc[3][0]); acc[3][1] = fma2(a3, w2.y, acc[3][1]);
        }
        __syncthreads();
    }

    float bv[4], vals[4][4];
#pragma unroll
    for (int j = 0; j < 4; j++) bv[j] = bias[f0 + 4 * tx + j];
#pragma unroll
    for (int i = 0; i < 4; i++) {
        float2 u0 = upk(acc[i][0]), u1 = upk(acc[i][1]);
        vals[i][0] = u0.x + bv[0]; vals[i][1] = u0.y + bv[1];
        vals[i][2] = u1.x + bv[2]; vals[i][3] = u1.y + bv[3];
    }

    if (p == 0) {
        // Qp: A-fragment order. u32 covers f-pair (f, f+1) for row n.
#pragma unroll
        for (int i = 0; i < 4; i++) {
            int n = n0 + 4 * ty + i;
            int wt = n >> 4, lr = n & 7, hi = (n >> 3) & 1;
#pragma unroll
            for (int jp = 0; jp < 4; jp += 2) {
                int f = f0 + 4 * tx + jp;
                unsigned u = pbf(vals[i][jp], vals[i][jp + 1]);
                int kblk = f >> 4;
                int a    = (((f >> 3) & 1) << 1) + hi;
                int lane = lr * 4 + ((f >> 1) & 3);
                g_Qp[(((b * 256 + wt) * 8 + kblk) * 32 + lane) * 4 + a] = u;
            }
        }
    } else if (p == 1) {
        // Kp: B-fragment order for S=QK^T (k-dim = f, n-dim = key).
#pragma unroll
        for (int i = 0; i < 4; i++) {
            int n = n0 + 4 * ty + i;              // key
            int kt = n >> 6, nt = (n & 63) >> 3, lr = n & 7;
#pragma unroll
            for (int jp = 0; jp < 4; jp += 2) {
                int f = f0 + 4 * tx + jp;
                unsigned u = pbf(vals[i][jp], vals[i][jp + 1]);
                int kblk  = f >> 4;
                int kpair = kblk >> 1;
                int pos   = ((kblk & 1) << 1) + ((f >> 3) & 1);
                int lane  = lr * 4 + ((f >> 1) & 3);
                g_Kp[((((b * 64 + kt) * 8 + nt) * 4 + kpair) * 32 + lane) * 4 + pos] = u;
            }
        }
    } else {
        // Vp: B-fragment order for O=PV (k-dim = key, n-dim = f). pack key-pairs.
#pragma unroll
        for (int ip = 0; ip < 4; ip += 2) {
            int n = n0 + 4 * ty + ip;             // even key
            int kt = n >> 6;
            int kblk  = (n & 63) >> 4;
            int kpair = kblk >> 1;
            int pos   = ((kblk & 1) << 1) + ((n >> 3) & 1);
            int cqv   = (n & 7) >> 1;
#pragma unroll
            for (int j = 0; j < 4; j++) {
                int f = f0 + 4 * tx + j;
                unsigned u = pbf(vals[ip][j], vals[ip + 1][j]);
                int nt   = f >> 3;
                int lane = (f & 7) * 4 + cqv;
                g_Vp[((((b * 64 + kt) * 16 + nt) * 2 + kpair) * 32 + lane) * 4 + pos] = u;
            }
        }
    }
}

// ============================================================================
// flash attention: 128 q-rows/CTA, 8 warps, bf16 m16n8k16.
// cp.async double-buffered K/V (16 KB each, frag order, contiguous).
// P: S C-fragments -> exp -> bf16x2 pack -> PV A-fragments, all in registers.
// SMEM: 2 x (K 16KB + V 16KB) = 64 KB
// ============================================================================
#define ATTN_SMEM (4096 * 16)

__global__ void __launch_bounds__(256, 1) attn_kernel()
{
    extern __shared__ __align__(16) uint4 smq[];
    // uint4 units: buf0 K [0,1024) V [1024,2048); buf1 K [2048,3072) V [3072,4096)

    int b  = blockIdx.y;
    int qt = blockIdx.x;
    int tid  = threadIdx.x;
    int w    = tid >> 5;
    int lane = tid & 31;

    // ---- Q fragments from global (A-frag order, coalesced uint4) ----
    uint4 qf[8];
    {
        const uint4* qsrc = (const uint4*)g_Qp + (size_t)(b * 256 + qt * 8 + w) * 8 * 32;
#pragma unroll
        for (int k = 0; k < 8; k++) qf[k] = __ldg(&qsrc[k * 32 + lane]);
    }

    float m0 = -3.0e38f, m1 = -3.0e38f, l0 = 0.0f, l1 = 0.0f;
    float oacc[16][4];
#pragma unroll
    for (int i = 0; i < 16; i++)
        oacc[i][0] = oacc[i][1] = oacc[i][2] = oacc[i][3] = 0.0f;

    const uint4* gk = (const uint4*)g_Kp + (size_t)b * 64 * 1024;
    const uint4* gv = (const uint4*)g_Vp + (size_t)b * 64 * 1024;
    unsigned smb = (unsigned)__cvta_generic_to_shared(smq);

    // prologue: stage tile 0 into buf 0
#pragma unroll
    for (int i = 0; i < 4; i++) {
        int idx = tid + i * 256;
        cp16(smb + idx * 16, gk + idx);
        cp16(smb + (1024 + idx) * 16, gv + idx);
    }
    asm volatile("cp.async.commit_group;" ::: "memory");

    for (int t = 0; t < 64; t++) {
        __syncthreads();   // compute reads of the buffer being overwritten are done
        if (t + 1 < 64) {
            unsigned kb = smb + ((t + 1) & 1) * 2048 * 16;
            const uint4* nk = gk + (t + 1) * 1024;
            const uint4* nv = gv + (t + 1) * 1024;
#pragma unroll
            for (int i = 0; i < 4; i++) {
                int idx = tid + i * 256;
                cp16(kb + idx * 16, nk + idx);
                cp16(kb + (1024 + idx) * 16, nv + idx);
            }
            asm volatile("cp.async.commit_group;" ::: "memory");
            asm volatile("cp.async.wait_group 1;" ::: "memory");
        } else {
            asm volatile("cp.async.wait_group 0;" ::: "memory");
        }
        __syncthreads();

        const uint4* Ks = smq + (t & 1) * 2048;
        const uint4* Vs = Ks + 1024;

        // ---- S = Q K^T : 8 key-tiles x 4 kpairs (2 mma per 16B load) ----
        float sacc[8][4];
#pragma unroll
        for (int nt = 0; nt < 8; nt++)
            sacc[nt][0] = sacc[nt][1] = sacc[nt][2] = sacc[nt][3] = 0.0f;
#pragma unroll
        for (int nt = 0; nt < 8; nt++) {
#pragma unroll
            for (int kp = 0; kp < 4; kp++) {
                uint4 kk = Ks[(nt * 4 + kp) * 32 + lane];
                mma_bf16(sacc[nt], (const unsigned*)&qf[2 * kp],     kk.x, kk.y);
                mma_bf16(sacc[nt], (const unsigned*)&qf[2 * kp + 1], kk.z, kk.w);
            }
        }

        // ---- online softmax; pack P straight into PV A-fragments ----
        float mx0 = -3.0e38f, mx1 = -3.0e38f;
#pragma unroll
        for (int nt = 0; nt < 8; nt++) {
            mx0 = fmaxf(mx0, fmaxf(sacc[nt][0], sacc[nt][1]));
            mx1 = fmaxf(mx1, fmaxf(sacc[nt][2], sacc[nt][3]));
        }
        mx0 = fmaxf(mx0, __shfl_xor_sync(0xffffffffu, mx0, 1));
        mx0 = fmaxf(mx0, __shfl_xor_sync(0xffffffffu, mx0, 2));
        mx1 = fmaxf(mx1, __shfl_xor_sync(0xffffffffu, mx1, 1));
        mx1 = fmaxf(mx1, __shfl_xor_sync(0xffffffffu, mx1, 2));
        float mn0 = fmaxf(m0, mx0), mn1 = fmaxf(m1, mx1);
        float al0 = __expf(m0 - mn0), al1 = __expf(m1 - mn1);
        float su0 = 0.0f, su1 = 0.0f;

        unsigned pf[4][4];
#pragma unroll
        for (int nt = 0; nt < 8; nt++) {
            float p00 = __expf(sacc[nt][0] - mn0);
            float p01 = __expf(sacc[nt][1] - mn0);
            float p10 = __expf(sacc[nt][2] - mn1);
            float p11 = __expf(sacc[nt][3] - mn1);
            su0 += p00 + p01; su1 += p10 + p11;
            int kb = nt >> 1;
            if ((nt & 1) == 0) {
                pf[kb][0] = pbf(p00, p01);   // row g,   keys 16kb+2cq..+1
                pf[kb][1] = pbf(p10, p11);   // row g+8
            } else {
                pf[kb][2] = pbf(p00, p01);   // row g,   keys 16kb+8+2cq..+1
                pf[kb][3] = pbf(p10, p11);   // row g+8
            }
        }
        su0 += __shfl_xor_sync(0xffffffffu, su0, 1);
        su0 += __shfl_xor_sync(0xffffffffu, su0, 2);
        su1 += __shfl_xor_sync(0xffffffffu, su1, 1);
        su1 += __shfl_xor_sync(0xffffffffu, su1, 2);
        l0 = l0 * al0 + su0;  l1 = l1 * al1 + su1;
        m0 = mn0;             m1 = mn1;

#pragma unroll
        for (int nt = 0; nt < 16; nt++) {
            oacc[nt][0] *= al0; oacc[nt][1] *= al0;
            oacc[nt][2] *= al1; oacc[nt][3] *= al1;
        }

        // ---- O += P V : 16 f-tiles x 2 kpairs (2 mma per 16B load) ----
#pragma unroll
        for (int nt = 0; nt < 16; nt++) {
#pragma unroll
            for (int kp = 0; kp < 2; kp++) {
                uint4 vv = Vs[(nt * 2 + kp) * 32 + lane];
                mma_bf16(oacc[nt], pf[2 * kp],     vv.x, vv.y);
                mma_bf16(oacc[nt], pf[2 * kp + 1], vv.z, vv.w);
            }
        }
    }

    // ---- y = O / l ----
    int g  = lane >> 2;
    int cq = lane & 3;
    float inv0 = 1.0f / l0, inv1 = 1.0f / l1;
    float* yb = g_y + (b * NN + qt * 128) * FF;
    int r0 = 16 * w + g;
#pragma unroll
    for (int nt = 0; nt < 16; nt++) {
        int col = nt * 8 + 2 * cq;
        *(float2*)&yb[r0 * FF + col]       = make_float2(oacc[nt][0] * inv0, oacc[nt][1] * inv0);
        *(float2*)&yb[(r0 + 8) * FF + col] = make_float2(oacc[nt][2] * inv1, oacc[nt][3] * inv1);
    }
}

// ============================================================================
// zconv: z[b,c,n] = sum_f Wz[c,f] * y[b,n,f] + bz[c]; per-tile LN partials.
// ============================================================================
#define ZCONV_SMEM (2 * 128 * 68 * 4)

__global__ void __launch_bounds__(256) zconv_kernel(
    const float* __restrict__ Wz, const float* __restrict__ bz)
{
    extern __shared__ __align__(16) float sm[];
    float* WzT = sm;
    float* YsT = sm + 128 * 68;

    int b  = blockIdx.z;
    int c0 = blockIdx.y * 64;
    int n0 = blockIdx.x * 64;
    int tid = threadIdx.x, tx = tid & 15, ty = tid >> 4;

    const float* yb = g_y + b * NN * FF;
    for (int i = tid; i < 64 * FF; i += 256) {
        int c = i >> 7, f = i & 127;
        WzT[f * 68 + c] = Wz[(c0 + c) * FF + f];
    }
    for (int i = tid; i < 64 * FF; i += 256) {
        int n = i >> 7, f = i & 127;
        YsT[f * 68 + n] = yb[(n0 + n) * FF + f];
    }
    __syncthreads();

    ull acc[4][2];
#pragma unroll
    for (int i = 0; i < 4; i++) { acc[i][0] = 0ULL; acc[i][1] = 0ULL; }
#pragma unroll 8
    for (int k = 0; k < FF; k++) {
        float4 a = *(const float4*)&WzT[k * 68 + 4 * ty];
        ulonglong2 yv = *(const ulonglong2*)&YsT[k * 68 + 4 * tx];
        ull a0 = dup2(a.x), a1 = dup2(a.y), a2 = dup2(a.z), a3 = dup2(a.w);
        acc[0][0] = fma2(a0, yv.x, acc[0][0]); acc[0][1] = fma2(a0, yv.y, acc[0][1]);
        acc[1][0] = fma2(a1, yv.x, acc[1][0]); acc[1][1] = fma2(a1, yv.y, acc[1][1]);
        acc[2][0] = fma2(a2, yv.x, acc[2][0]); acc[2][1] = fma2(a2, yv.y, acc[2][1]);
        acc[3][0] = fma2(a3, yv.x, acc[3][0]); acc[3][1] = fma2(a3, yv.y, acc[3][1]);
    }

    float lsum = 0.0f, lsq = 0.0f;
    float* zb = g_z + b * CC * NN;
#pragma unroll
    for (int i = 0; i < 4; i++) {
        float bzv = bz[c0 + 4 * ty + i];
        float2 u0 = upk(acc[i][0]), u1 = upk(acc[i][1]);
        float z0 = u0.x + bzv, z1 = u0.y + bzv, z2 = u1.x + bzv, z3 = u1.y + bzv;
        *(float4*)&zb[(c0 + 4 * ty + i) * NN + n0 + 4 * tx] = make_float4(z0, z1, z2, z3);
        lsum += z0 + z1 + z2 + z3;
        lsq  += z0 * z0 + z1 * z1 + z2 * z2 + z3 * z3;
    }

    __syncthreads();
    float* rs = sm;
    float* rq = sm + 256;
    rs[tid] = lsum; rq[tid] = lsq;
    __syncthreads();
#pragma unroll
    for (int s = 128; s > 0; s >>= 1) {
        if (tid < s) { rs[tid] += rs[tid + s]; rq[tid] += rq[tid + s]; }
        __syncthreads();
    }
    if (tid == 0)
        g_part[b * 256 + blockIdx.y * 64 + blockIdx.x] = make_float2(rs[0], rq[0]);
}

// ============================================================================
__global__ void stats_kernel()
{
    __shared__ float rs[256], rq[256];
    int b = blockIdx.x, tid = threadIdx.x;
    float2 v = g_part[b * 256 + tid];
    rs[tid] = v.x; rq[tid] = v.y;
    __syncthreads();
#pragma unroll
    for (int s = 128; s > 0; s >>= 1) {
        if (tid < s) { rs[tid] += rs[tid + s]; rq[tid] += rq[tid + s]; }
        __syncthreads();
    }
    if (tid == 0) {
        float inv  = 1.0f / (float)(CC * NN);
        float mean = rs[0] * inv;
        float var  = rq[0] * inv - mean * mean;
        g_stats[b] = make_float2(mean, rsqrtf(var + LN_EPS));
    }
}

// ============================================================================
__global__ void __launch_bounds__(256) ln_kernel(
    const float* __restrict__ x,
    const float* __restrict__ lw, const float* __restrict__ lb,
    float* __restrict__ out)
{
    int idx = blockIdx.x * 256 + threadIdx.x;
    int b = idx >> 18;
    int r = idx & 262143;
    float2 st = g_stats[b];
    float4 z  = ((const float4*)g_z)[idx];
    float4 xv = ((const float4*)x)[idx];
    float4 w  = ((const float4*)lw)[r];
    float4 bb = ((const float4*)lb)[r];
    float4 o;
    o.x = (z.x - st.x) * st.y * w.x + bb.x + xv.x;
    o.y = (z.y - st.x) * st.y * w.y + bb.y + xv.y;
    o.z = (z.z - st.x) * st.y * w.z + bb.z + xv.z;
    o.w = (z.w - st.x) * st.y * w.w + bb.w + xv.w;
    ((float4*)out)[idx] = o;
}

// ============================================================================
extern "C" void kernel_launch(void* const* d_in, const int* in_sizes, int n_in,
                              void* d_out, int out_size)
{
    const float* x  = (const float*)d_in[0];
    const float* Wg = (const float*)d_in[1];
    const float* bg = (const float*)d_in[2];
    const float* Wt = (const float*)d_in[3];
    const float* bt = (const float*)d_in[4];
    const float* Wp = (const float*)d_in[5];
    const float* bp = (const float*)d_in[6];
    const float* Wz = (const float*)d_in[7];
    const float* bz = (const float*)d_in[8];
    const float* lw = (const float*)d_in[9];
    const float* lb = (const float*)d_in[10];
    float* out = (float*)d_out;

    cudaFuncSetAttribute(attn_kernel,  cudaFuncAttributeMaxDynamicSharedMemorySize, ATTN_SMEM);
    cudaFuncSetAttribute(zconv_kernel, cudaFuncAttributeMaxDynamicSharedMemorySize, ZCONV_SMEM);

    proj_kernel <<<dim3(NN / 64, 6, BB), 256>>>(x, Wt, bt, Wp, bp, Wg, bg);
    attn_kernel <<<dim3(NN / 128, BB), 256, ATTN_SMEM>>>();
    zconv_kernel<<<dim3(NN / 64, CC / 64, BB), 256, ZCONV_SMEM>>>(Wz, bz);
    stats_kernel<<<BB, 256>>>();
    ln_kernel   <<<(BB * CC * NN / 4) / 256, 256>>>(x, lw, lb, out);
}